// round 5
// baseline (speedup 1.0000x reference)
#include <cuda_runtime.h>
#include <cuda_bf16.h>
#include <cstdint>

#define K_DIM 256
#define N_DIM 256
#define MAX_NODES 100000
#define MAX_EDGES 800000
#define SCAN_BLK 1024
#define MAX_SCAN_BLOCKS ((MAX_NODES + SCAN_BLK - 1) / SCAN_BLK)

// Static device scratch (allocation-free rule)
__device__ float g_supp[(size_t)MAX_NODES * N_DIM];
__device__ __nv_bfloat16 g_whi[K_DIM * N_DIM];
__device__ __nv_bfloat16 g_wlo[K_DIM * N_DIM];
__device__ int   g_deg[MAX_NODES];
__device__ int   g_off[MAX_NODES];
__device__ int   g_rank[MAX_EDGES];
__device__ int   g_bsum[MAX_SCAN_BLOCKS];
__device__ int   g_src_s[MAX_EDGES];
__device__ float g_w_s[MAX_EDGES];

// ---------------------------------------------------------------------------
// Kernel 0: convert + transpose W -> bf16 hi/lo in B-operand layout [n][k]
// ---------------------------------------------------------------------------
__global__ void convert_w_kernel(const float* __restrict__ W,
                                 __nv_bfloat16* __restrict__ whi,
                                 __nv_bfloat16* __restrict__ wlo) {
    int k = blockIdx.x;
    int n = threadIdx.x;
    float v = W[k * N_DIM + n];
    __nv_bfloat16 h = __float2bfloat16(v);
    float lo = v - __bfloat162float(h);
    whi[n * K_DIM + k] = h;
    wlo[n * K_DIM + k] = __float2bfloat16(lo);
}

// ---------------------------------------------------------------------------
// CSR build: zero -> hist(+rank) -> scan(3) -> scatter (no atomics)
// ---------------------------------------------------------------------------
__global__ void zero_deg_kernel(int* __restrict__ deg, int N) {
    int i = blockIdx.x * blockDim.x + threadIdx.x;
    if (i < N) deg[i] = 0;
}

__global__ void hist_rank_kernel(const int* __restrict__ edst,
                                 int* __restrict__ deg,
                                 int* __restrict__ rank, int E) {
    int i = blockIdx.x * blockDim.x + threadIdx.x;
    if (i < E) rank[i] = atomicAdd(&deg[edst[i]], 1);
}

__global__ __launch_bounds__(SCAN_BLK) void scan1_kernel(
    const int* __restrict__ deg, int* __restrict__ off, int* __restrict__ bsum, int N) {
    __shared__ int s[SCAN_BLK];
    int tid = threadIdx.x;
    int gid = blockIdx.x * SCAN_BLK + tid;
    int v = (gid < N) ? deg[gid] : 0;
    s[tid] = v;
    __syncthreads();
#pragma unroll
    for (int d = 1; d < SCAN_BLK; d <<= 1) {
        int t = (tid >= d) ? s[tid - d] : 0;
        __syncthreads();
        s[tid] += t;
        __syncthreads();
    }
    if (gid < N) off[gid] = s[tid] - v;          // exclusive
    if (tid == SCAN_BLK - 1) bsum[blockIdx.x] = s[tid];
}

__global__ __launch_bounds__(SCAN_BLK) void scan2_kernel(int* __restrict__ bsum, int nb) {
    __shared__ int s[SCAN_BLK];
    int tid = threadIdx.x;
    int v = (tid < nb) ? bsum[tid] : 0;
    s[tid] = v;
    __syncthreads();
#pragma unroll
    for (int d = 1; d < SCAN_BLK; d <<= 1) {
        int t = (tid >= d) ? s[tid - d] : 0;
        __syncthreads();
        s[tid] += t;
        __syncthreads();
    }
    if (tid < nb) bsum[tid] = s[tid] - v;        // exclusive
}

__global__ void scan3_kernel(int* __restrict__ off, const int* __restrict__ bsum, int N) {
    int gid = blockIdx.x * blockDim.x + threadIdx.x;
    if (gid < N) off[gid] += bsum[gid / SCAN_BLK];
}

__global__ void scatter_kernel(const int* __restrict__ esrc,
                               const int* __restrict__ edst,
                               const float* __restrict__ ew,
                               const int* __restrict__ off,
                               const int* __restrict__ rank,
                               int* __restrict__ src_s,
                               float* __restrict__ w_s, int E) {
    int e = blockIdx.x * blockDim.x + threadIdx.x;
    if (e < E) {
        int pos = off[edst[e]] + rank[e];
        src_s[pos] = esrc[e];
        w_s[pos] = ew[e];
    }
}

// ---------------------------------------------------------------------------
// Aggregate: one warp per dst node; 4-edge batches for MLP; out = agg + bias
// ---------------------------------------------------------------------------
__global__ __launch_bounds__(256) void agg_kernel(
    const float* __restrict__ supp,
    const int* __restrict__ src_s,
    const float* __restrict__ w_s,
    const int* __restrict__ off,
    const float* __restrict__ bias,
    float* __restrict__ out,
    int N, int E) {

    const int warp = (blockIdx.x * blockDim.x + threadIdx.x) >> 5;
    const int lane = threadIdx.x & 31;
    if (warp >= N) return;

    const int beg = __ldg(&off[warp]);
    const int end = (warp + 1 < N) ? __ldg(&off[warp + 1]) : E;

    const float4* bias4 = reinterpret_cast<const float4*>(bias);
    float4 acc0 = bias4[lane * 2];
    float4 acc1 = bias4[lane * 2 + 1];

    const int c0 = lane * 2;
    const int c1 = lane * 2 + 1;

    int j = beg;
#pragma unroll 1
    for (; j + 4 <= end; j += 4) {
        int s0 = __ldg(&src_s[j + 0]);
        int s1 = __ldg(&src_s[j + 1]);
        int s2 = __ldg(&src_s[j + 2]);
        int s3 = __ldg(&src_s[j + 3]);
        float w0 = __ldg(&w_s[j + 0]);
        float w1 = __ldg(&w_s[j + 1]);
        float w2 = __ldg(&w_s[j + 2]);
        float w3 = __ldg(&w_s[j + 3]);

        const float4* r0 = reinterpret_cast<const float4*>(supp + (size_t)s0 * N_DIM);
        const float4* r1 = reinterpret_cast<const float4*>(supp + (size_t)s1 * N_DIM);
        const float4* r2 = reinterpret_cast<const float4*>(supp + (size_t)s2 * N_DIM);
        const float4* r3 = reinterpret_cast<const float4*>(supp + (size_t)s3 * N_DIM);

        float4 a0 = __ldg(&r0[c0]), b0 = __ldg(&r0[c1]);
        float4 a1 = __ldg(&r1[c0]), b1 = __ldg(&r1[c1]);
        float4 a2 = __ldg(&r2[c0]), b2 = __ldg(&r2[c1]);
        float4 a3 = __ldg(&r3[c0]), b3 = __ldg(&r3[c1]);

        acc0.x = fmaf(a0.x, w0, acc0.x); acc0.y = fmaf(a0.y, w0, acc0.y);
        acc0.z = fmaf(a0.z, w0, acc0.z); acc0.w = fmaf(a0.w, w0, acc0.w);
        acc1.x = fmaf(b0.x, w0, acc1.x); acc1.y = fmaf(b0.y, w0, acc1.y);
        acc1.z = fmaf(b0.z, w0, acc1.z); acc1.w = fmaf(b0.w, w0, acc1.w);

        acc0.x = fmaf(a1.x, w1, acc0.x); acc0.y = fmaf(a1.y, w1, acc0.y);
        acc0.z = fmaf(a1.z, w1, acc0.z); acc0.w = fmaf(a1.w, w1, acc0.w);
        acc1.x = fmaf(b1.x, w1, acc1.x); acc1.y = fmaf(b1.y, w1, acc1.y);
        acc1.z = fmaf(b1.z, w1, acc1.z); acc1.w = fmaf(b1.w, w1, acc1.w);

        acc0.x = fmaf(a2.x, w2, acc0.x); acc0.y = fmaf(a2.y, w2, acc0.y);
        acc0.z = fmaf(a2.z, w2, acc0.z); acc0.w = fmaf(a2.w, w2, acc0.w);
        acc1.x = fmaf(b2.x, w2, acc1.x); acc1.y = fmaf(b2.y, w2, acc1.y);
        acc1.z = fmaf(b2.z, w2, acc1.z); acc1.w = fmaf(b2.w, w2, acc1.w);

        acc0.x = fmaf(a3.x, w3, acc0.x); acc0.y = fmaf(a3.y, w3, acc0.y);
        acc0.z = fmaf(a3.z, w3, acc0.z); acc0.w = fmaf(a3.w, w3, acc0.w);
        acc1.x = fmaf(b3.x, w3, acc1.x); acc1.y = fmaf(b3.y, w3, acc1.y);
        acc1.z = fmaf(b3.z, w3, acc1.z); acc1.w = fmaf(b3.w, w3, acc1.w);
    }
#pragma unroll 1
    for (; j < end; ++j) {
        const int src = __ldg(&src_s[j]);
        const float w = __ldg(&w_s[j]);
        const float4* srow = reinterpret_cast<const float4*>(supp + (size_t)src * N_DIM);
        float4 a = __ldg(&srow[c0]);
        float4 b = __ldg(&srow[c1]);
        acc0.x = fmaf(a.x, w, acc0.x); acc0.y = fmaf(a.y, w, acc0.y);
        acc0.z = fmaf(a.z, w, acc0.z); acc0.w = fmaf(a.w, w, acc0.w);
        acc1.x = fmaf(b.x, w, acc1.x); acc1.y = fmaf(b.y, w, acc1.y);
        acc1.z = fmaf(b.z, w, acc1.z); acc1.w = fmaf(b.w, w, acc1.w);
    }

    float4* drow = reinterpret_cast<float4*>(out + (size_t)warp * N_DIM);
    drow[c0] = acc0;
    drow[c1] = acc1;
}

// ---------------------------------------------------------------------------
// Kernel 2: bf16-split GEMM via mma.sync (HMMA), supp[M,256] = x[M,256] @ W
// ---------------------------------------------------------------------------
#define BM 128
#define BN 128
#define BK 32
#define LDS 40
#define TILE_BYTES (128 * LDS * 2)
#define OFF_AHI 0
#define OFF_ALO (TILE_BYTES)
#define OFF_BHI (2 * TILE_BYTES)
#define OFF_BLO (3 * TILE_BYTES)
#define STAGE_BYTES (4 * TILE_BYTES)
#define GEMM_SMEM (2 * STAGE_BYTES)

__device__ __forceinline__ uint32_t smem_u32(const void* p) {
    uint32_t a;
    asm("{ .reg .u64 t; cvta.to.shared.u64 t, %1; cvt.u32.u64 %0, t; }" : "=r"(a) : "l"(p));
    return a;
}

__device__ __forceinline__ void ldm_x4(uint32_t addr, uint32_t r[4]) {
    asm volatile("ldmatrix.sync.aligned.m8n8.x4.shared.b16 {%0,%1,%2,%3}, [%4];"
                 : "=r"(r[0]), "=r"(r[1]), "=r"(r[2]), "=r"(r[3]) : "r"(addr));
}

__device__ __forceinline__ void mma_bf16(float c[4], const uint32_t a[4],
                                         const uint32_t b[2]) {
    asm volatile(
        "mma.sync.aligned.m16n8k16.row.col.f32.bf16.bf16.f32 "
        "{%0,%1,%2,%3}, {%4,%5,%6,%7}, {%8,%9}, {%0,%1,%2,%3};"
        : "+f"(c[0]), "+f"(c[1]), "+f"(c[2]), "+f"(c[3])
        : "r"(a[0]), "r"(a[1]), "r"(a[2]), "r"(a[3]), "r"(b[0]), "r"(b[1]));
}

__device__ __forceinline__ void split2(float x, float y, uint32_t& hp, uint32_t& lp) {
    __nv_bfloat16 hx = __float2bfloat16(x);
    __nv_bfloat16 hy = __float2bfloat16(y);
    __nv_bfloat16 lx = __float2bfloat16(x - __bfloat162float(hx));
    __nv_bfloat16 ly = __float2bfloat16(y - __bfloat162float(hy));
    __nv_bfloat162 h2(hx, hy), l2(lx, ly);
    hp = *reinterpret_cast<uint32_t*>(&h2);
    lp = *reinterpret_cast<uint32_t*>(&l2);
}

__global__ __launch_bounds__(256, 1) void gemm_mma_kernel(
    const float* __restrict__ x,
    float* __restrict__ supp,
    const __nv_bfloat16* __restrict__ whi,
    const __nv_bfloat16* __restrict__ wlo,
    int M) {

    extern __shared__ __align__(128) char smem[];
    const uint32_t sbase = smem_u32(smem);

    const int tid = threadIdx.x;
    const int wid = tid >> 5;
    const int lane = tid & 31;
    const int rowBase = blockIdx.y * BM;
    const int colBase = blockIdx.x * BN;

    const int warp_m = (wid >> 2) * 64;
    const int warp_n = (wid & 3) * 32;

    const int ld_row = tid >> 1;
    const int ld_kc  = (tid & 1) * 16;
    const int a_grow = rowBase + ld_row;
    const bool a_ok = (a_grow < M);
    const float4* x4 = reinterpret_cast<const float4*>(x);
    const uint4* bhi4 = reinterpret_cast<const uint4*>(whi + (size_t)(colBase + ld_row) * K_DIM);
    const uint4* blo4 = reinterpret_cast<const uint4*>(wlo + (size_t)(colBase + ld_row) * K_DIM);

    const int a_lr = lane & 15;
    const int a_lk = (lane >> 4) * 8;
    const int b_ln = ((lane >> 4) * 8) + (lane & 7);
    const int b_lk = ((lane >> 3) & 1) * 8;

    float acc[4][4][4];
#pragma unroll
    for (int i = 0; i < 4; i++)
#pragma unroll
        for (int j = 0; j < 4; j++)
#pragma unroll
            for (int q = 0; q < 4; q++) acc[i][j][q] = 0.0f;

    float4 ga[4];
    uint4 gbh[2], gbl[2];

    auto load_chunk = [&](int k0) {
#pragma unroll
        for (int j = 0; j < 4; j++) {
            ga[j] = a_ok ? x4[(size_t)a_grow * (K_DIM / 4) + ((k0 + ld_kc) >> 2) + j]
                         : make_float4(0.f, 0.f, 0.f, 0.f);
        }
#pragma unroll
        for (int j = 0; j < 2; j++) {
            gbh[j] = bhi4[((k0 + ld_kc) >> 3) + j];
            gbl[j] = blo4[((k0 + ld_kc) >> 3) + j];
        }
    };

    auto store_chunk = [&](int s) {
        char* st = smem + s * STAGE_BYTES;
        uint32_t a_off = ld_row * (LDS * 2) + ld_kc * 2;
#pragma unroll
        for (int j = 0; j < 4; j++) {
            uint32_t hp0, lp0, hp1, lp1;
            split2(ga[j].x, ga[j].y, hp0, lp0);
            split2(ga[j].z, ga[j].w, hp1, lp1);
            *reinterpret_cast<uint2*>(st + OFF_AHI + a_off + j * 8) = make_uint2(hp0, hp1);
            *reinterpret_cast<uint2*>(st + OFF_ALO + a_off + j * 8) = make_uint2(lp0, lp1);
        }
#pragma unroll
        for (int j = 0; j < 2; j++) {
            *reinterpret_cast<uint4*>(st + OFF_BHI + a_off + j * 16) = gbh[j];
            *reinterpret_cast<uint4*>(st + OFF_BLO + a_off + j * 16) = gbl[j];
        }
    };

    auto compute_chunk = [&](int s) {
        uint32_t base = sbase + s * STAGE_BYTES;
#pragma unroll
        for (int ks = 0; ks < 2; ks++) {
            uint32_t ah[4][4], al[4][4];
#pragma unroll
            for (int mi = 0; mi < 4; mi++) {
                uint32_t row = warp_m + mi * 16 + a_lr;
                uint32_t off = row * (LDS * 2) + (ks * 16 + a_lk) * 2;
                ldm_x4(base + OFF_AHI + off, ah[mi]);
                ldm_x4(base + OFF_ALO + off, al[mi]);
            }
            uint32_t bh[4][2], bl[4][2];
#pragma unroll
            for (int pi = 0; pi < 2; pi++) {
                uint32_t row = warp_n + pi * 16 + b_ln;
                uint32_t off = row * (LDS * 2) + (ks * 16 + b_lk) * 2;
                uint32_t r[4], rl[4];
                ldm_x4(base + OFF_BHI + off, r);
                ldm_x4(base + OFF_BLO + off, rl);
                bh[pi * 2][0] = r[0]; bh[pi * 2][1] = r[1];
                bh[pi * 2 + 1][0] = r[2]; bh[pi * 2 + 1][1] = r[3];
                bl[pi * 2][0] = rl[0]; bl[pi * 2][1] = rl[1];
                bl[pi * 2 + 1][0] = rl[2]; bl[pi * 2 + 1][1] = rl[3];
            }
#pragma unroll
            for (int mi = 0; mi < 4; mi++) {
#pragma unroll
                for (int ni = 0; ni < 4; ni++) {
                    mma_bf16(acc[mi][ni], ah[mi], bh[ni]);
                    mma_bf16(acc[mi][ni], ah[mi], bl[ni]);
                    mma_bf16(acc[mi][ni], al[mi], bh[ni]);
                }
            }
        }
    };

    load_chunk(0);
    store_chunk(0);
    __syncthreads();

#pragma unroll 1
    for (int c = 0; c < K_DIM / BK; ++c) {
        if (c < K_DIM / BK - 1) load_chunk((c + 1) * BK);
        compute_chunk(c & 1);
        if (c < K_DIM / BK - 1) {
            store_chunk((c + 1) & 1);
        }
        __syncthreads();
    }

    const int lrow = lane >> 2;
    const int lcol = (lane & 3) * 2;
#pragma unroll
    for (int mi = 0; mi < 4; mi++) {
#pragma unroll
        for (int half = 0; half < 2; half++) {
            int grow = rowBase + warp_m + mi * 16 + lrow + half * 8;
            if (grow < M) {
                float* dst = supp + (size_t)grow * N_DIM + colBase + warp_n;
#pragma unroll
                for (int ni = 0; ni < 4; ni++) {
                    float2 v = half ? make_float2(acc[mi][ni][2], acc[mi][ni][3])
                                    : make_float2(acc[mi][ni][0], acc[mi][ni][1]);
                    *reinterpret_cast<float2*>(dst + ni * 8 + lcol) = v;
                }
            }
        }
    }
}

// ---------------------------------------------------------------------------
// Launch
// ---------------------------------------------------------------------------
extern "C" void kernel_launch(void* const* d_in, const int* in_sizes, int n_in,
                              void* d_out, int out_size) {
    const float* x      = (const float*)d_in[0];
    const float* weight = (const float*)d_in[1];
    const float* bias   = (const float*)d_in[2];
    const float* ew     = (const float*)d_in[3];
    const int*   esrc   = (const int*)d_in[4];
    const int*   edst   = (const int*)d_in[5];
    float* out = (float*)d_out;

    const int M = in_sizes[0] / K_DIM;   // 100000
    const int E = in_sizes[3];           // 800000

    float* supp;          cudaGetSymbolAddress((void**)&supp, g_supp);
    __nv_bfloat16* whi;   cudaGetSymbolAddress((void**)&whi, g_whi);
    __nv_bfloat16* wlo;   cudaGetSymbolAddress((void**)&wlo, g_wlo);
    int* deg;             cudaGetSymbolAddress((void**)&deg, g_deg);
    int* off;             cudaGetSymbolAddress((void**)&off, g_off);
    int* rank;            cudaGetSymbolAddress((void**)&rank, g_rank);
    int* bsum;            cudaGetSymbolAddress((void**)&bsum, g_bsum);
    int* src_s;           cudaGetSymbolAddress((void**)&src_s, g_src_s);
    float* w_s;           cudaGetSymbolAddress((void**)&w_s, g_w_s);

    static bool attr_set = false;
    if (!attr_set) {
        cudaFuncSetAttribute(gemm_mma_kernel,
                             cudaFuncAttributeMaxDynamicSharedMemorySize, GEMM_SMEM);
        attr_set = true;
    }

    const int nblk_scan = (M + SCAN_BLK - 1) / SCAN_BLK;

    // 0) W -> bf16 hi/lo
    convert_w_kernel<<<K_DIM, N_DIM>>>(weight, whi, wlo);

    // 1) CSR build
    zero_deg_kernel<<<(M + 255) / 256, 256>>>(deg, M);
    hist_rank_kernel<<<(E + 255) / 256, 256>>>(edst, deg, rank, E);
    scan1_kernel<<<nblk_scan, SCAN_BLK>>>(deg, off, bsum, M);
    scan2_kernel<<<1, SCAN_BLK>>>(bsum, nblk_scan);
    scan3_kernel<<<(M + 255) / 256, 256>>>(off, bsum, M);
    scatter_kernel<<<(E + 255) / 256, 256>>>(esrc, edst, ew, off, rank, src_s, w_s, E);

    // 2) supp = x @ W  (HMMA bf16 split)
    {
        dim3 grid(N_DIM / BN, (M + BM - 1) / BM);
        gemm_mma_kernel<<<grid, 256, GEMM_SMEM>>>(x, supp, whi, wlo, M);
    }

    // 3) per-node gather-aggregate: out = segment_sum + bias
    {
        int warps_per_block = 256 / 32;
        int blocks = (M + warps_per_block - 1) / warps_per_block;
        agg_kernel<<<blocks, 256>>>(supp, src_s, w_s, off, bias, out, M, E);
    }
}

// round 6
// speedup vs baseline: 1.0814x; 1.0814x over previous
#include <cuda_runtime.h>
#include <cuda_bf16.h>
#include <cstdint>

#define K_DIM 256
#define N_DIM 256
#define MAX_NODES 100000
#define MAX_EDGES 800000
#define SCAN_BLK 1024
#define MAX_SCAN_BLOCKS ((MAX_NODES + SCAN_BLK - 1) / SCAN_BLK)

// Static device scratch (allocation-free rule)
__device__ float g_supp[(size_t)MAX_NODES * N_DIM];
__device__ __nv_bfloat16 g_whi[K_DIM * N_DIM];
__device__ __nv_bfloat16 g_wlo[K_DIM * N_DIM];
__device__ int   g_deg[MAX_NODES];
__device__ int   g_off[MAX_NODES];
__device__ int   g_rank[MAX_EDGES];
__device__ int   g_bsum[MAX_SCAN_BLOCKS];
__device__ int   g_src_s[MAX_EDGES];
__device__ float g_w_s[MAX_EDGES];

// ---------------------------------------------------------------------------
// Kernel 0: convert + transpose W -> bf16 hi/lo in B-operand layout [n][k]
// ---------------------------------------------------------------------------
__global__ void convert_w_kernel(const float* __restrict__ W,
                                 __nv_bfloat16* __restrict__ whi,
                                 __nv_bfloat16* __restrict__ wlo) {
    int k = blockIdx.x;
    int n = threadIdx.x;
    float v = W[k * N_DIM + n];
    __nv_bfloat16 h = __float2bfloat16(v);
    float lo = v - __bfloat162float(h);
    whi[n * K_DIM + k] = h;
    wlo[n * K_DIM + k] = __float2bfloat16(lo);
}

// ---------------------------------------------------------------------------
// CSR build: zero -> hist(+rank) -> scan(3) -> scatter (no atomics)
// ---------------------------------------------------------------------------
__global__ void zero_deg_kernel(int* __restrict__ deg, int N) {
    int i = blockIdx.x * blockDim.x + threadIdx.x;
    if (i < N) deg[i] = 0;
}

__global__ void hist_rank_kernel(const int* __restrict__ edst,
                                 int* __restrict__ deg,
                                 int* __restrict__ rank, int E) {
    int i = blockIdx.x * blockDim.x + threadIdx.x;
    if (i < E) rank[i] = atomicAdd(&deg[edst[i]], 1);
}

__global__ __launch_bounds__(SCAN_BLK) void scan1_kernel(
    const int* __restrict__ deg, int* __restrict__ off, int* __restrict__ bsum, int N) {
    __shared__ int s[SCAN_BLK];
    int tid = threadIdx.x;
    int gid = blockIdx.x * SCAN_BLK + tid;
    int v = (gid < N) ? deg[gid] : 0;
    s[tid] = v;
    __syncthreads();
#pragma unroll
    for (int d = 1; d < SCAN_BLK; d <<= 1) {
        int t = (tid >= d) ? s[tid - d] : 0;
        __syncthreads();
        s[tid] += t;
        __syncthreads();
    }
    if (gid < N) off[gid] = s[tid] - v;          // exclusive
    if (tid == SCAN_BLK - 1) bsum[blockIdx.x] = s[tid];
}

__global__ __launch_bounds__(SCAN_BLK) void scan2_kernel(int* __restrict__ bsum, int nb) {
    __shared__ int s[SCAN_BLK];
    int tid = threadIdx.x;
    int v = (tid < nb) ? bsum[tid] : 0;
    s[tid] = v;
    __syncthreads();
#pragma unroll
    for (int d = 1; d < SCAN_BLK; d <<= 1) {
        int t = (tid >= d) ? s[tid - d] : 0;
        __syncthreads();
        s[tid] += t;
        __syncthreads();
    }
    if (tid < nb) bsum[tid] = s[tid] - v;        // exclusive
}

__global__ void scan3_kernel(int* __restrict__ off, const int* __restrict__ bsum, int N) {
    int gid = blockIdx.x * blockDim.x + threadIdx.x;
    if (gid < N) off[gid] += bsum[gid / SCAN_BLK];
}

__global__ void scatter_kernel(const int* __restrict__ esrc,
                               const int* __restrict__ edst,
                               const float* __restrict__ ew,
                               const int* __restrict__ off,
                               const int* __restrict__ rank,
                               int* __restrict__ src_s,
                               float* __restrict__ w_s, int E) {
    int e = blockIdx.x * blockDim.x + threadIdx.x;
    if (e < E) {
        int pos = off[edst[e]] + rank[e];
        src_s[pos] = esrc[e];
        w_s[pos] = ew[e];
    }
}

// ---------------------------------------------------------------------------
// Aggregate: one warp per dst node; register accumulation; out = agg + bias
// (R4 form — measured at the L2 gather floor; batching regressed it)
// ---------------------------------------------------------------------------
__global__ __launch_bounds__(256) void agg_kernel(
    const float* __restrict__ supp,
    const int* __restrict__ src_s,
    const float* __restrict__ w_s,
    const int* __restrict__ off,
    const float* __restrict__ bias,
    float* __restrict__ out,
    int N, int E) {

    const int warp = (blockIdx.x * blockDim.x + threadIdx.x) >> 5;
    const int lane = threadIdx.x & 31;
    if (warp >= N) return;

    const int beg = off[warp];
    const int end = (warp + 1 < N) ? off[warp + 1] : E;

    const float4* bias4 = reinterpret_cast<const float4*>(bias);
    float4 acc0 = bias4[lane * 2];
    float4 acc1 = bias4[lane * 2 + 1];

    for (int j = beg; j < end; ++j) {
        const int src = __ldg(&src_s[j]);
        const float w = __ldg(&w_s[j]);
        const float4* srow = reinterpret_cast<const float4*>(supp + (size_t)src * N_DIM);
        float4 a = __ldg(&srow[lane * 2]);
        float4 b = __ldg(&srow[lane * 2 + 1]);
        acc0.x = fmaf(a.x, w, acc0.x); acc0.y = fmaf(a.y, w, acc0.y);
        acc0.z = fmaf(a.z, w, acc0.z); acc0.w = fmaf(a.w, w, acc0.w);
        acc1.x = fmaf(b.x, w, acc1.x); acc1.y = fmaf(b.y, w, acc1.y);
        acc1.z = fmaf(b.z, w, acc1.z); acc1.w = fmaf(b.w, w, acc1.w);
    }

    float4* drow = reinterpret_cast<float4*>(out + (size_t)warp * N_DIM);
    drow[lane * 2] = acc0;
    drow[lane * 2 + 1] = acc1;
}

// ---------------------------------------------------------------------------
// Kernel 2: bf16-split GEMM via mma.sync (HMMA), supp[M,256] = x[M,256] @ W
// ---------------------------------------------------------------------------
#define BM 128
#define BN 128
#define BK 32
#define LDS 40
#define TILE_BYTES (128 * LDS * 2)
#define OFF_AHI 0
#define OFF_ALO (TILE_BYTES)
#define OFF_BHI (2 * TILE_BYTES)
#define OFF_BLO (3 * TILE_BYTES)
#define STAGE_BYTES (4 * TILE_BYTES)
#define GEMM_SMEM (2 * STAGE_BYTES)

__device__ __forceinline__ uint32_t smem_u32(const void* p) {
    uint32_t a;
    asm("{ .reg .u64 t; cvta.to.shared.u64 t, %1; cvt.u32.u64 %0, t; }" : "=r"(a) : "l"(p));
    return a;
}

__device__ __forceinline__ void ldm_x4(uint32_t addr, uint32_t r[4]) {
    asm volatile("ldmatrix.sync.aligned.m8n8.x4.shared.b16 {%0,%1,%2,%3}, [%4];"
                 : "=r"(r[0]), "=r"(r[1]), "=r"(r[2]), "=r"(r[3]) : "r"(addr));
}

__device__ __forceinline__ void mma_bf16(float c[4], const uint32_t a[4],
                                         const uint32_t b[2]) {
    asm volatile(
        "mma.sync.aligned.m16n8k16.row.col.f32.bf16.bf16.f32 "
        "{%0,%1,%2,%3}, {%4,%5,%6,%7}, {%8,%9}, {%0,%1,%2,%3};"
        : "+f"(c[0]), "+f"(c[1]), "+f"(c[2]), "+f"(c[3])
        : "r"(a[0]), "r"(a[1]), "r"(a[2]), "r"(a[3]), "r"(b[0]), "r"(b[1]));
}

__device__ __forceinline__ void split2(float x, float y, uint32_t& hp, uint32_t& lp) {
    __nv_bfloat16 hx = __float2bfloat16(x);
    __nv_bfloat16 hy = __float2bfloat16(y);
    __nv_bfloat16 lx = __float2bfloat16(x - __bfloat162float(hx));
    __nv_bfloat16 ly = __float2bfloat16(y - __bfloat162float(hy));
    __nv_bfloat162 h2(hx, hy), l2(lx, ly);
    hp = *reinterpret_cast<uint32_t*>(&h2);
    lp = *reinterpret_cast<uint32_t*>(&l2);
}

__global__ __launch_bounds__(256, 1) void gemm_mma_kernel(
    const float* __restrict__ x,
    float* __restrict__ supp,
    const __nv_bfloat16* __restrict__ whi,
    const __nv_bfloat16* __restrict__ wlo,
    int M) {

    extern __shared__ __align__(128) char smem[];
    const uint32_t sbase = smem_u32(smem);

    const int tid = threadIdx.x;
    const int wid = tid >> 5;
    const int lane = tid & 31;
    const int rowBase = blockIdx.y * BM;
    const int colBase = blockIdx.x * BN;

    const int warp_m = (wid >> 2) * 64;
    const int warp_n = (wid & 3) * 32;

    const int ld_row = tid >> 1;
    const int ld_kc  = (tid & 1) * 16;
    const int a_grow = rowBase + ld_row;
    const bool a_ok = (a_grow < M);
    const float4* x4 = reinterpret_cast<const float4*>(x);
    const uint4* bhi4 = reinterpret_cast<const uint4*>(whi + (size_t)(colBase + ld_row) * K_DIM);
    const uint4* blo4 = reinterpret_cast<const uint4*>(wlo + (size_t)(colBase + ld_row) * K_DIM);

    const int a_lr = lane & 15;
    const int a_lk = (lane >> 4) * 8;
    const int b_ln = ((lane >> 4) * 8) + (lane & 7);
    const int b_lk = ((lane >> 3) & 1) * 8;

    float acc[4][4][4];
#pragma unroll
    for (int i = 0; i < 4; i++)
#pragma unroll
        for (int j = 0; j < 4; j++)
#pragma unroll
            for (int q = 0; q < 4; q++) acc[i][j][q] = 0.0f;

    float4 ga[4];
    uint4 gbh[2], gbl[2];

    auto load_chunk = [&](int k0) {
#pragma unroll
        for (int j = 0; j < 4; j++) {
            ga[j] = a_ok ? x4[(size_t)a_grow * (K_DIM / 4) + ((k0 + ld_kc) >> 2) + j]
                         : make_float4(0.f, 0.f, 0.f, 0.f);
        }
#pragma unroll
        for (int j = 0; j < 2; j++) {
            gbh[j] = bhi4[((k0 + ld_kc) >> 3) + j];
            gbl[j] = blo4[((k0 + ld_kc) >> 3) + j];
        }
    };

    auto store_chunk = [&](int s) {
        char* st = smem + s * STAGE_BYTES;
        uint32_t a_off = ld_row * (LDS * 2) + ld_kc * 2;
#pragma unroll
        for (int j = 0; j < 4; j++) {
            uint32_t hp0, lp0, hp1, lp1;
            split2(ga[j].x, ga[j].y, hp0, lp0);
            split2(ga[j].z, ga[j].w, hp1, lp1);
            *reinterpret_cast<uint2*>(st + OFF_AHI + a_off + j * 8) = make_uint2(hp0, hp1);
            *reinterpret_cast<uint2*>(st + OFF_ALO + a_off + j * 8) = make_uint2(lp0, lp1);
        }
#pragma unroll
        for (int j = 0; j < 2; j++) {
            *reinterpret_cast<uint4*>(st + OFF_BHI + a_off + j * 16) = gbh[j];
            *reinterpret_cast<uint4*>(st + OFF_BLO + a_off + j * 16) = gbl[j];
        }
    };

    auto compute_chunk = [&](int s) {
        uint32_t base = sbase + s * STAGE_BYTES;
#pragma unroll
        for (int ks = 0; ks < 2; ks++) {
            uint32_t ah[4][4], al[4][4];
#pragma unroll
            for (int mi = 0; mi < 4; mi++) {
                uint32_t row = warp_m + mi * 16 + a_lr;
                uint32_t off = row * (LDS * 2) + (ks * 16 + a_lk) * 2;
                ldm_x4(base + OFF_AHI + off, ah[mi]);
                ldm_x4(base + OFF_ALO + off, al[mi]);
            }
            uint32_t bh[4][2], bl[4][2];
#pragma unroll
            for (int pi = 0; pi < 2; pi++) {
                uint32_t row = warp_n + pi * 16 + b_ln;
                uint32_t off = row * (LDS * 2) + (ks * 16 + b_lk) * 2;
                uint32_t r[4], rl[4];
                ldm_x4(base + OFF_BHI + off, r);
                ldm_x4(base + OFF_BLO + off, rl);
                bh[pi * 2][0] = r[0]; bh[pi * 2][1] = r[1];
                bh[pi * 2 + 1][0] = r[2]; bh[pi * 2 + 1][1] = r[3];
                bl[pi * 2][0] = rl[0]; bl[pi * 2][1] = rl[1];
                bl[pi * 2 + 1][0] = rl[2]; bl[pi * 2 + 1][1] = rl[3];
            }
#pragma unroll
            for (int mi = 0; mi < 4; mi++) {
#pragma unroll
                for (int ni = 0; ni < 4; ni++) {
                    mma_bf16(acc[mi][ni], ah[mi], bh[ni]);
                    mma_bf16(acc[mi][ni], ah[mi], bl[ni]);
                    mma_bf16(acc[mi][ni], al[mi], bh[ni]);
                }
            }
        }
    };

    load_chunk(0);
    store_chunk(0);
    __syncthreads();

#pragma unroll 1
    for (int c = 0; c < K_DIM / BK; ++c) {
        if (c < K_DIM / BK - 1) load_chunk((c + 1) * BK);
        compute_chunk(c & 1);
        if (c < K_DIM / BK - 1) {
            store_chunk((c + 1) & 1);
        }
        __syncthreads();
    }

    const int lrow = lane >> 2;
    const int lcol = (lane & 3) * 2;
#pragma unroll
    for (int mi = 0; mi < 4; mi++) {
#pragma unroll
        for (int half = 0; half < 2; half++) {
            int grow = rowBase + warp_m + mi * 16 + lrow + half * 8;
            if (grow < M) {
                float* dst = supp + (size_t)grow * N_DIM + colBase + warp_n;
#pragma unroll
                for (int ni = 0; ni < 4; ni++) {
                    float2 v = half ? make_float2(acc[mi][ni][2], acc[mi][ni][3])
                                    : make_float2(acc[mi][ni][0], acc[mi][ni][1]);
                    *reinterpret_cast<float2*>(dst + ni * 8 + lcol) = v;
                }
            }
        }
    }
}

// ---------------------------------------------------------------------------
// Launch — CSR build forked onto a side stream, overlapped with the GEMM.
// Stream/events created once on the first (non-captured correctness) call.
// ---------------------------------------------------------------------------
extern "C" void kernel_launch(void* const* d_in, const int* in_sizes, int n_in,
                              void* d_out, int out_size) {
    const float* x      = (const float*)d_in[0];
    const float* weight = (const float*)d_in[1];
    const float* bias   = (const float*)d_in[2];
    const float* ew     = (const float*)d_in[3];
    const int*   esrc   = (const int*)d_in[4];
    const int*   edst   = (const int*)d_in[5];
    float* out = (float*)d_out;

    const int M = in_sizes[0] / K_DIM;   // 100000
    const int E = in_sizes[3];           // 800000

    float* supp;          cudaGetSymbolAddress((void**)&supp, g_supp);
    __nv_bfloat16* whi;   cudaGetSymbolAddress((void**)&whi, g_whi);
    __nv_bfloat16* wlo;   cudaGetSymbolAddress((void**)&wlo, g_wlo);
    int* deg;             cudaGetSymbolAddress((void**)&deg, g_deg);
    int* off;             cudaGetSymbolAddress((void**)&off, g_off);
    int* rank;            cudaGetSymbolAddress((void**)&rank, g_rank);
    int* bsum;            cudaGetSymbolAddress((void**)&bsum, g_bsum);
    int* src_s;           cudaGetSymbolAddress((void**)&src_s, g_src_s);
    float* w_s;           cudaGetSymbolAddress((void**)&w_s, g_w_s);

    static cudaStream_t s_side = nullptr;
    static cudaEvent_t  s_fork = nullptr, s_join = nullptr;
    static bool s_init = false;
    if (!s_init) {
        cudaFuncSetAttribute(gemm_mma_kernel,
                             cudaFuncAttributeMaxDynamicSharedMemorySize, GEMM_SMEM);
        cudaStreamCreateWithFlags(&s_side, cudaStreamNonBlocking);
        cudaEventCreateWithFlags(&s_fork, cudaEventDisableTiming);
        cudaEventCreateWithFlags(&s_join, cudaEventDisableTiming);
        s_init = true;
    }

    const int nblk_scan = (M + SCAN_BLK - 1) / SCAN_BLK;

    // Fork: side stream builds CSR while main stream runs convert + GEMM.
    cudaEventRecord(s_fork, 0);
    cudaStreamWaitEvent(s_side, s_fork, 0);

    // --- side stream: CSR build (independent of GEMM) ---
    zero_deg_kernel<<<(M + 255) / 256, 256, 0, s_side>>>(deg, M);
    hist_rank_kernel<<<(E + 255) / 256, 256, 0, s_side>>>(edst, deg, rank, E);
    scan1_kernel<<<nblk_scan, SCAN_BLK, 0, s_side>>>(deg, off, bsum, M);
    scan2_kernel<<<1, SCAN_BLK, 0, s_side>>>(bsum, nblk_scan);
    scan3_kernel<<<(M + 255) / 256, 256, 0, s_side>>>(off, bsum, M);
    scatter_kernel<<<(E + 255) / 256, 256, 0, s_side>>>(esrc, edst, ew, off, rank,
                                                        src_s, w_s, E);
    cudaEventRecord(s_join, s_side);

    // --- main stream: convert + GEMM ---
    convert_w_kernel<<<K_DIM, N_DIM>>>(weight, whi, wlo);
    {
        dim3 grid(N_DIM / BN, (M + BM - 1) / BM);
        gemm_mma_kernel<<<grid, 256, GEMM_SMEM>>>(x, supp, whi, wlo, M);
    }

    // Join: agg needs both GEMM output and CSR arrays.
    cudaStreamWaitEvent(0, s_join, 0);

    // --- per-node gather-aggregate: out = segment_sum + bias ---
    {
        int warps_per_block = 256 / 32;
        int blocks = (M + warps_per_block - 1) / warps_per_block;
        agg_kernel<<<blocks, 256>>>(supp, src_s, w_s, off, bias, out, M, E);
    }
}